// round 13
// baseline (speedup 1.0000x reference)
#include <cuda_runtime.h>
#include <cuda_bf16.h>
#include <math.h>
#include <stdint.h>

#define NUM_LAYERS 4
#define N_NODES 50000
#define N_PAD   50048            // 391 * 128
#define N_EDGES 800000
#define IN_FEAT 256
#define HIDDEN  512
#define MTILES  391

// ---------------- CSR scratch ----------------
__device__ int g_deg[N_NODES];
__device__ int g_row_ptr[N_NODES + 1];
__device__ int g_wptr[N_NODES];
__device__ int g_col[N_EDGES];

// ---------------- operand buffers ----------------
__device__ __align__(16) __nv_bfloat16 g_xh[(size_t)N_PAD * IN_FEAT];
__device__ __align__(16) __nv_bfloat16 g_xl[(size_t)N_PAD * IN_FEAT];
__device__ __align__(16) __nv_bfloat16 g_sh[(size_t)NUM_LAYERS * N_PAD * HIDDEN];
__device__ __align__(16) __nv_bfloat16 g_sl[(size_t)NUM_LAYERS * N_PAD * HIDDEN];
__device__ __align__(16) float         g_y [(size_t)NUM_LAYERS * N_PAD * HIDDEN];
__device__ __align__(16) float         g_a [(size_t)NUM_LAYERS * N_PAD * HIDDEN];
__device__ __align__(16) __nv_bfloat16 g_o1h[(size_t)N_PAD * HIDDEN];
__device__ __align__(16) __nv_bfloat16 g_o1l[(size_t)N_PAD * HIDDEN];
__device__ __align__(16) __nv_bfloat16 g_o2h[(size_t)N_PAD * HIDDEN];
__device__ __align__(16) __nv_bfloat16 g_o2l[(size_t)N_PAD * HIDDEN];
#define W1_ELEMS (131072 + 3 * 262144)
#define W2_ELEMS (4 * 262144)
__device__ __align__(16) __nv_bfloat16 g_w1h[W1_ELEMS];
__device__ __align__(16) __nv_bfloat16 g_w1l[W1_ELEMS];
__device__ __align__(16) __nv_bfloat16 g_w2h[W2_ELEMS];
__device__ __align__(16) __nv_bfloat16 g_w2l[W2_ELEMS];

// ---------------- helpers ----------------
__device__ __forceinline__ uint32_t smem_u32(const void* p) {
    uint32_t a;
    asm("{ .reg .u64 t; cvta.to.shared.u64 t, %1; cvt.u32.u64 %0, t; }"
        : "=r"(a) : "l"(p));
    return a;
}

__device__ __forceinline__ void cpa16(uint32_t dst, const void* src) {
    asm volatile("cp.async.cg.shared.global [%0], [%1], 16;"
                 :: "r"(dst), "l"(src) : "memory");
}
#define CP_COMMIT() asm volatile("cp.async.commit_group;" ::: "memory")
#define CP_WAIT(n)  asm volatile("cp.async.wait_group %0;" :: "n"(n) : "memory")

#define LDSM4(r0, r1, r2, r3, addr)                                            \
    asm volatile("ldmatrix.sync.aligned.m8n8.x4.shared.b16 {%0,%1,%2,%3}, [%4];" \
                 : "=r"(r0), "=r"(r1), "=r"(r2), "=r"(r3) : "r"(addr))

#define MMA16816(c, a0, a1, a2, a3, b0, b1)                                    \
    asm volatile("mma.sync.aligned.m16n8k16.row.col.f32.bf16.bf16.f32 "        \
                 "{%0,%1,%2,%3},{%4,%5,%6,%7},{%8,%9},{%0,%1,%2,%3};"          \
                 : "+f"((c)[0]), "+f"((c)[1]), "+f"((c)[2]), "+f"((c)[3])      \
                 : "r"(a0), "r"(a1), "r"(a2), "r"(a3), "r"(b0), "r"(b1))

__device__ __forceinline__ void split_bf16(float v, __nv_bfloat16& h, __nv_bfloat16& l) {
    h = __float2bfloat16_rn(v);
    l = __float2bfloat16_rn(v - __bfloat162float(h));
}

// fast tanh: 1 - 2/(e^{2x}+1); abs err ~1e-7
__device__ __forceinline__ float fast_tanh(float x) {
    float t = __expf(2.0f * x);
    return 1.0f - __fdividef(2.0f, t + 1.0f);
}

// ================= CSR build =================
__global__ void k_zero_deg() {
    for (int i = blockIdx.x * blockDim.x + threadIdx.x; i < N_NODES;
         i += gridDim.x * blockDim.x)
        g_deg[i] = 0;
}

__global__ void k_hist(const int* __restrict__ ei) {
    int e = blockIdx.x * blockDim.x + threadIdx.x;
    if (e < N_EDGES) {
        int dst = ei[N_EDGES + e];
        if ((unsigned)dst < (unsigned)N_NODES) atomicAdd(&g_deg[dst], 1);
    }
}

__global__ void k_scan() {
    __shared__ int buf[1024];
    int t = threadIdx.x;
    int carry = 0;
    for (int base = 0; base < N_NODES; base += 1024) {
        int i = base + t;
        int v = (i < N_NODES) ? g_deg[i] : 0;
        buf[t] = v;
        __syncthreads();
#pragma unroll
        for (int off = 1; off < 1024; off <<= 1) {
            int tmp = (t >= off) ? buf[t - off] : 0;
            __syncthreads();
            buf[t] += tmp;
            __syncthreads();
        }
        int incl = buf[t];
        if (i < N_NODES) {
            g_row_ptr[i + 1] = carry + incl;
            g_wptr[i]        = carry + incl - v;
        }
        carry += buf[1023];
        __syncthreads();
    }
    if (t == 0) g_row_ptr[0] = 0;
}

__global__ void k_scatter(const int* __restrict__ ei) {
    int e = blockIdx.x * blockDim.x + threadIdx.x;
    if (e < N_EDGES) {
        int src = ei[e];
        int dst = ei[N_EDGES + e];
        if ((unsigned)dst < (unsigned)N_NODES && (unsigned)src < (unsigned)N_NODES) {
            int pos = atomicAdd(&g_wptr[dst], 1);
            g_col[pos] = src;
        }
    }
}

// ================= conversions =================
__global__ void k_convert_x(const float* __restrict__ x) {
    const int groups = N_PAD * IN_FEAT / 4;
    for (int g = blockIdx.x * blockDim.x + threadIdx.x; g < groups;
         g += gridDim.x * blockDim.x) {
        int e = g * 4;
        int m = e / IN_FEAT;
        float4 v = make_float4(0.f, 0.f, 0.f, 0.f);
        if (m < N_NODES) v = *(const float4*)&x[e];
        __nv_bfloat16 h0, h1, h2, h3, l0, l1, l2, l3;
        split_bf16(v.x, h0, l0); split_bf16(v.y, h1, l1);
        split_bf16(v.z, h2, l2); split_bf16(v.w, h3, l3);
        *(__nv_bfloat162*)&g_xh[e]     = __halves2bfloat162(h0, h1);
        *(__nv_bfloat162*)&g_xh[e + 2] = __halves2bfloat162(h2, h3);
        *(__nv_bfloat162*)&g_xl[e]     = __halves2bfloat162(l0, l1);
        *(__nv_bfloat162*)&g_xl[e + 2] = __halves2bfloat162(l2, l3);
    }
}

__global__ void k_convert_w(const float* __restrict__ Wi0,
                            const float* __restrict__ Wi_rest,
                            const float* __restrict__ Wr) {
    for (int g = blockIdx.x * blockDim.x + threadIdx.x; g < W1_ELEMS / 4;
         g += gridDim.x * blockDim.x) {
        int e = g * 4;
        float4 v = (e < 131072) ? *(const float4*)&Wi0[e]
                                : *(const float4*)&Wi_rest[e - 131072];
        __nv_bfloat16 h0, h1, h2, h3, l0, l1, l2, l3;
        split_bf16(v.x, h0, l0); split_bf16(v.y, h1, l1);
        split_bf16(v.z, h2, l2); split_bf16(v.w, h3, l3);
        *(__nv_bfloat162*)&g_w1h[e]     = __halves2bfloat162(h0, h1);
        *(__nv_bfloat162*)&g_w1h[e + 2] = __halves2bfloat162(h2, h3);
        *(__nv_bfloat162*)&g_w1l[e]     = __halves2bfloat162(l0, l1);
        *(__nv_bfloat162*)&g_w1l[e + 2] = __halves2bfloat162(l2, l3);
    }
    for (int g = blockIdx.x * blockDim.x + threadIdx.x; g < W2_ELEMS / 4;
         g += gridDim.x * blockDim.x) {
        int e = g * 4;
        float4 v = *(const float4*)&Wr[e];
        __nv_bfloat16 h0, h1, h2, h3, l0, l1, l2, l3;
        split_bf16(v.x, h0, l0); split_bf16(v.y, h1, l1);
        split_bf16(v.z, h2, l2); split_bf16(v.w, h3, l3);
        *(__nv_bfloat162*)&g_w2h[e]     = __halves2bfloat162(h0, h1);
        *(__nv_bfloat162*)&g_w2h[e + 2] = __halves2bfloat162(h2, h3);
        *(__nv_bfloat162*)&g_w2l[e]     = __halves2bfloat162(l0, l1);
        *(__nv_bfloat162*)&g_w2l[e + 2] = __halves2bfloat162(l2, l3);
    }
}

// states [4, N_NODES, 512] fp32 -> g_sh/g_sl [4, N_PAD, 512] bf16 (pad zeros)
__global__ void k_convert_s(const float* __restrict__ states) {
    const size_t groups = (size_t)NUM_LAYERS * N_PAD * HIDDEN / 4;
    for (size_t g = blockIdx.x * (size_t)blockDim.x + threadIdx.x; g < groups;
         g += (size_t)gridDim.x * blockDim.x) {
        size_t e   = g * 4;
        int    l   = (int)(e / ((size_t)N_PAD * HIDDEN));
        size_t rem = e - (size_t)l * N_PAD * HIDDEN;
        int    nd  = (int)(rem / HIDDEN);
        int    col = (int)(rem % HIDDEN);
        float4 v = make_float4(0.f, 0.f, 0.f, 0.f);
        if (nd < N_NODES)
            v = *(const float4*)&states[((size_t)l * N_NODES + nd) * HIDDEN + col];
        __nv_bfloat16 h0, h1, h2, h3, l0, l1, l2, l3;
        split_bf16(v.x, h0, l0); split_bf16(v.y, h1, l1);
        split_bf16(v.z, h2, l2); split_bf16(v.w, h3, l3);
        *(__nv_bfloat162*)&g_sh[e]     = __halves2bfloat162(h0, h1);
        *(__nv_bfloat162*)&g_sh[e + 2] = __halves2bfloat162(h2, h3);
        *(__nv_bfloat162*)&g_sl[e]     = __halves2bfloat162(l0, l1);
        *(__nv_bfloat162*)&g_sl[e + 2] = __halves2bfloat162(l2, l3);
    }
}

// ================= fp32 aggregation of Y: A[n] = sum_{e:dst==n} Y[src] ======
__global__ __launch_bounds__(128)
void k_aggr_f32(const float* __restrict__ Y, float* __restrict__ A) {
    const int node = blockIdx.x;
    if (node >= N_NODES) return;
    const int t = threadIdx.x;                  // one float4 column each
    const float4* S = (const float4*)Y;

    float4 acc = make_float4(0.f, 0.f, 0.f, 0.f);
    int beg = g_row_ptr[node];
    int end = g_row_ptr[node + 1];
    int e = beg;
    for (; e + 4 <= end; e += 4) {
        int s0 = g_col[e],     s1 = g_col[e + 1];
        int s2 = g_col[e + 2], s3 = g_col[e + 3];
        float4 v0 = S[(size_t)s0 * (HIDDEN / 4) + t];
        float4 v1 = S[(size_t)s1 * (HIDDEN / 4) + t];
        float4 v2 = S[(size_t)s2 * (HIDDEN / 4) + t];
        float4 v3 = S[(size_t)s3 * (HIDDEN / 4) + t];
        acc.x += v0.x + v1.x + v2.x + v3.x;
        acc.y += v0.y + v1.y + v2.y + v3.y;
        acc.z += v0.z + v1.z + v2.z + v3.z;
        acc.w += v0.w + v1.w + v2.w + v3.w;
    }
    for (; e < end; e++) {
        float4 v = S[(size_t)g_col[e] * (HIDDEN / 4) + t];
        acc.x += v.x; acc.y += v.y; acc.z += v.z; acc.w += v.w;
    }
    ((float4*)A)[(size_t)node * (HIDDEN / 4) + t] = acc;
}

// ================= mma.sync split GEMM, two epilogue modes =================
// CTA tile 128x128x32; 8 warps 2(M)x4(N); warp tile 64x32.
// 2-stage cp.async double buffer = 81920 B SMEM => 2 CTAs/SM.
// mode 0 (Y):  C = A @ B^T, plain fp32 store; B selected per-layer via
//              blockIdx.y / MTILES (batched over 4 layers).
// mode 1 (Z):  out = a*tanh(C + Aadd) + (1-a)*s_old, + bf16 split of out.
#define ROWP 40
#define TE   (128 * ROWP)              // elems per tile = 5120
#define STAGE_E (4 * TE)               // elems per stage = 20480
#define SMEM_BYTES (2 * STAGE_E * 2)   // 81920 B

__device__ __forceinline__ void load_stage(
    uint32_t sbase,
    const __nv_bfloat16* __restrict__ Ah, const __nv_bfloat16* __restrict__ Al,
    const __nv_bfloat16* __restrict__ Bh, const __nv_bfloat16* __restrict__ Bl,
    int bm, int n0, int kof, int K, int tid)
{
#pragma unroll
    for (int j = 0; j < 2; j++) {
        int idx = tid + j * 256;   // 0..511
        int r = idx >> 2;
        int c = idx & 3;
        uint32_t d = sbase + (uint32_t)(r * ROWP + c * 8) * 2;
        size_t ga = (size_t)(bm + r) * K + kof + c * 8;
        size_t gb = (size_t)(n0 + r) * K + kof + c * 8;
        cpa16(d,              Ah + ga);
        cpa16(d + TE * 2,     Al + ga);
        cpa16(d + 2 * TE * 2, Bh + gb);
        cpa16(d + 3 * TE * 2, Bl + gb);
    }
}

__global__ __launch_bounds__(296, 2)
void k_gemm(const __nv_bfloat16* __restrict__ Ah,
            const __nv_bfloat16* __restrict__ Al,
            const __nv_bfloat16* __restrict__ BhB,
            const __nv_bfloat16* __restrict__ BlB,
            int K, int c1, int mode,
            const float* __restrict__ Aadd,
            const float* __restrict__ s_old,
            const float* __restrict__ leak,
            float* __restrict__ outp,
            __nv_bfloat16* __restrict__ oh,
            __nv_bfloat16* __restrict__ ol)
{
    extern __shared__ __nv_bfloat16 smem[];
    const uint32_t sm0 = smem_u32(smem);

    const int tid  = threadIdx.x;
    const int wid  = tid >> 5;
    const int lane = tid & 31;
    const int wm   = wid & 1;       // 0..1 (M)
    const int wn   = wid >> 1;      // 0..3 (N)
    const int bm   = blockIdx.y * 128;
    const int n0   = blockIdx.x * 128;

    const __nv_bfloat16* Bh = BhB;
    const __nv_bfloat16* Bl = BlB;
    if (mode == 0) {
        int layer = blockIdx.y / MTILES;     // 391 M-tiles per layer
        Bh += (size_t)layer * 262144;
        Bl += (size_t)layer * 262144;
    }

    float acc[4][4][4];
#pragma unroll
    for (int i = 0; i < 4; i++)
#pragma unroll
        for (int j = 0; j < 4; j++)
#pragma unroll
            for (int q = 0; q < 4; q++) acc[i][j][q] = 0.f;

    // prologue: chunk 0
    load_stage(sm0, Ah, Al, Bh, Bl, bm, n0, 0, K, tid);
    CP_COMMIT();

    // ldmatrix lane-address components
    const int arow = (lane & 7) + ((lane >> 3) & 1) * 8;   // + wm*64 + mi*16
    const int acol = (lane >> 4) * 8;                       // + ks*16
    const int brow = (lane & 7) + (lane >> 4) * 8;          // + wn*32 + ng2*16
    const int bcol = ((lane >> 3) & 1) * 8;                 // + ks*16

    for (int ci = 0; ci < c1; ci++) {
        if (ci + 1 < c1) {
            uint32_t sb = sm0 + (uint32_t)(((ci + 1) & 1) * STAGE_E) * 2;
            load_stage(sb, Ah, Al, Bh, Bl, bm, n0, (ci + 1) * 32, K, tid);
            CP_COMMIT();
            CP_WAIT(1);
        } else {
            CP_WAIT(0);
        }
        __syncthreads();

        const uint32_t sb = sm0 + (uint32_t)((ci & 1) * STAGE_E) * 2;
        const uint32_t aB = sb + (uint32_t)((wm * 64 + arow) * ROWP + acol) * 2;
        const uint32_t bB = sb + (uint32_t)(2 * TE + (wn * 32 + brow) * ROWP + bcol) * 2;

#pragma unroll
        for (int ks = 0; ks < 2; ks++) {
            // staged fragments: af holds A-hi first, then is REUSED for A-lo.
            uint32_t af[4][4], bh[4][2], bl[4][2];
#pragma unroll
            for (int g2 = 0; g2 < 2; g2++) {
                uint32_t bd = bB + (uint32_t)(g2 * 16 * ROWP + ks * 16) * 2;
                uint32_t t0, t1, t2, t3;
                LDSM4(t0, t1, t2, t3, bd);
                bh[2 * g2][0] = t0; bh[2 * g2][1] = t1;
                bh[2 * g2 + 1][0] = t2; bh[2 * g2 + 1][1] = t3;
                LDSM4(t0, t1, t2, t3, bd + TE * 2);
                bl[2 * g2][0] = t0; bl[2 * g2][1] = t1;
                bl[2 * g2 + 1][0] = t2; bl[2 * g2 + 1][1] = t3;
            }
#pragma unroll
            for (int mi = 0; mi < 4; mi++) {
                uint32_t ad = aB + (uint32_t)(mi * 16 * ROWP + ks * 16) * 2;
                LDSM4(af[mi][0], af[mi][1], af[mi][2], af[mi][3], ad);
            }
            // hh
#pragma unroll
            for (int mi = 0; mi < 4; mi++)
#pragma unroll
                for (int ni = 0; ni < 4; ni++)
                    MMA16816(acc[mi][ni], af[mi][0], af[mi][1], af[mi][2], af[mi][3],
                             bh[ni][0], bh[ni][1]);
            // hl
#pragma unroll
            for (int mi = 0; mi < 4; mi++)
#pragma unroll
                for (int ni = 0; ni < 4; ni++)
                    MMA16816(acc[mi][ni], af[mi][0], af[mi][1], af[mi][2], af[mi][3],
                             bl[ni][0], bl[ni][1]);
            // reload A-lo, then lh
#pragma unroll
            for (int mi = 0; mi < 4; mi++) {
                uint32_t ad = aB + (uint32_t)(mi * 16 * ROWP + ks * 16) * 2 + TE * 2;
                LDSM4(af[mi][0], af[mi][1], af[mi][2], af[mi][3], ad);
            }
#pragma unroll
            for (int mi = 0; mi < 4; mi++)
#pragma unroll
                for (int ni = 0; ni < 4; ni++)
                    MMA16816(acc[mi][ni], af[mi][0], af[mi][1], af[mi][2], af[mi][3],
                             bh[ni][0], bh[ni][1]);
        }
        __syncthreads();
    }

    // ---------------- epilogue ----------------
    if (mode == 0) {
        // plain fp32 store into Y (all rows valid; buffer is padded)
#pragma unroll
        for (int mi = 0; mi < 4; mi++) {
#pragma unroll
            for (int h = 0; h < 2; h++) {
                int mm = bm + wm * 64 + mi * 16 + (lane >> 2) + h * 8;
                size_t rowb = (size_t)mm * HIDDEN + n0 + wn * 32 + (lane & 3) * 2;
#pragma unroll
                for (int ni = 0; ni < 4; ni++)
                    *(float2*)&outp[rowb + ni * 8] =
                        make_float2(acc[mi][ni][2 * h], acc[mi][ni][2 * h + 1]);
            }
        }
        return;
    }

    const float a   = leak[0];
    const float oma = 1.0f - a;
#pragma unroll
    for (int mi = 0; mi < 4; mi++) {
#pragma unroll
        for (int h = 0; h < 2; h++) {
            int mm = bm + wm * 64 + mi * 16 + (lane >> 2) + h * 8;
            bool valid = (mm < N_NODES);
            size_t rowb = (size_t)mm * HIDDEN + n0 + wn * 32 + (lane & 3) * 2;
#pragma unroll
            for (int ni = 0; ni < 4; ni++) {
                size_t off = rowb + ni * 8;
                if (valid) {
                    float2 ad = *(const float2*)&Aadd[off];
                    float2 s  = *(const float2*)&s_old[off];
                    float o0 = a * fast_tanh(acc[mi][ni][2 * h]     + ad.x) + oma * s.x;
                    float o1 = a * fast_tanh(acc[mi][ni][2 * h + 1] + ad.y) + oma * s.y;
                    *(float2*)&outp[off] = make_float2(o0, o1);
                    if (oh) {
                        __nv_bfloat16 h0, h1, l0, l1;
                        split_bf16(o0, h0, l0);
                        split_bf16(o1, h1, l1);
                        *(__nv_bfloat162*)&oh[off] = __halves2bfloat162(h0, h1);
                        *(__nv_bfloat162*)&ol[off] = __halves2bfloat162(l0, l1);
                    }
                } else if (oh) {
                    __nv_bfloat162 z =
                        __halves2bfloat162(__float2bfloat16_rn(0.f),
                                           __float2bfloat16_rn(0.f));
                    *(__nv_bfloat162*)&oh[off] = z;
                    *(__nv_bfloat162*)&ol[off] = z;
                }
            }
        }
    }
}

// ================= launch =================
extern "C" void kernel_launch(void* const* d_in, const int* in_sizes, int n_in,
                              void* d_out, int out_size)
{
    const int*   ei      = (const int*)d_in[0];       // [2, E] int32
    const float* x       = (const float*)d_in[1];     // [N, 256]
    const float* states  = (const float*)d_in[2];     // [4, N, 512]
    const float* Wi0     = (const float*)d_in[3];     // [512, 256]
    const float* Wi_rest = (const float*)d_in[4];     // [3, 512, 512]
    const float* Wr      = (const float*)d_in[5];     // [4, 512, 512]
    const float* leak    = (const float*)d_in[6];     // [1]
    float*       out     = (float*)d_out;             // [4, N, 512]

    (void)in_sizes; (void)n_in; (void)out_size;

    // One-time setup. CRITICAL: device addresses of __device__ symbols must be
    // resolved via cudaGetSymbolAddress — the bare symbol name in host code is
    // a host-side shadow (round-12 bug: GB300 ATS dereferenced host memory).
    static cudaStream_t sAg = nullptr;
    static cudaEvent_t evFork = nullptr;
    static cudaEvent_t evA[NUM_LAYERS];
    static __nv_bfloat16 *p_xh, *p_xl, *p_sh, *p_sl;
    static __nv_bfloat16 *p_o1h, *p_o1l, *p_o2h, *p_o2l;
    static __nv_bfloat16 *p_w1h, *p_w1l, *p_w2h, *p_w2l;
    static float *yptr, *aptr;
    if (sAg == nullptr) {
        cudaFuncSetAttribute(k_gemm,
                             cudaFuncAttributeMaxDynamicSharedMemorySize,
                             SMEM_BYTES);
        cudaStreamCreateWithFlags(&sAg, cudaStreamNonBlocking);
        cudaEventCreateWithFlags(&evFork, cudaEventDisableTiming);
        for (int l = 0; l < NUM_LAYERS; l++)
            cudaEventCreateWithFlags(&evA[l], cudaEventDisableTiming);
        cudaGetSymbolAddress((void**)&p_xh,  g_xh);
        cudaGetSymbolAddress((void**)&p_xl,  g_xl);
        cudaGetSymbolAddress((void**)&p_sh,  g_sh);
        cudaGetSymbolAddress((void**)&p_sl,  g_sl);
        cudaGetSymbolAddress((void**)&p_o1h, g_o1h);
        cudaGetSymbolAddress((void**)&p_o1l, g_o1l);
        cudaGetSymbolAddress((void**)&p_o2h, g_o2h);
        cudaGetSymbolAddress((void**)&p_o2l, g_o2l);
        cudaGetSymbolAddress((void**)&p_w1h, g_w1h);
        cudaGetSymbolAddress((void**)&p_w1l, g_w1l);
        cudaGetSymbolAddress((void**)&p_w2h, g_w2h);
        cudaGetSymbolAddress((void**)&p_w2l, g_w2l);
        cudaGetSymbolAddress((void**)&yptr,  g_y);
        cudaGetSymbolAddress((void**)&aptr,  g_a);
    }

    // ---- main stream: CSR build + operand conversions ----
    k_zero_deg<<<128, 256>>>();
    k_hist<<<(N_EDGES + 255) / 256, 256>>>(ei);
    k_scan<<<1, 1024>>>();
    k_scatter<<<(N_EDGES + 255) / 256, 256>>>(ei);
    k_convert_x<<<4096, 256>>>(x);
    k_convert_w<<<1024, 256>>>(Wi0, Wi_rest, Wr);
    k_convert_s<<<8192, 256>>>(states);

    // ---- batched Y-GEMM: Y[l] = states[l] @ Wr[l]^T, all 4 layers ----
    k_gemm<<<dim3(HIDDEN / 128, NUM_LAYERS * MTILES), 256, SMEM_BYTES>>>(
        p_sh, p_sl, p_w2h, p_w2l, HIDDEN, HIDDEN / 32, /*mode=*/0,
        nullptr, nullptr, nullptr, yptr, nullptr, nullptr);

    // ---- aggr0 on main (prioritized), then fork side for aggr1-3 ----
    k_aggr_f32<<<N_PAD, 128>>>(yptr, aptr);
    cudaEventRecord(evFork, 0);
    cudaStreamWaitEvent(sAg, evFork, 0);
    for (int l = 1; l < NUM_LAYERS; l++) {
        k_aggr_f32<<<N_PAD, 128, 0, sAg>>>(yptr + (size_t)l * N_PAD * HIDDEN,
                                           aptr + (size_t)l * N_PAD * HIDDEN);
        cudaEventRecord(evA[l], sAg);
    }

    // ---- sequential Z-GEMM chain (Z_l = inp_l @ Wi_l^T + fused epilogue) ----
    const __nv_bfloat16* a1h[4] = {p_xh, p_o1h, p_o2h, p_o1h};
    const __nv_bfloat16* a1l[4] = {p_xl, p_o1l, p_o2l, p_o1l};
    __nv_bfloat16* ohv[4] = {p_o1h, p_o2h, p_o1h, nullptr};
    __nv_bfloat16* olv[4] = {p_o1l, p_o2l, p_o1l, nullptr};
    dim3 grid(HIDDEN / 128, MTILES);
    for (int l = 0; l < NUM_LAYERS; l++) {
        int K1 = (l == 0) ? IN_FEAT : HIDDEN;
        const size_t w1off = (l == 0) ? 0 : (size_t)131072 + (size_t)(l - 1) * 262144;
        if (l > 0) cudaStreamWaitEvent(0, evA[l], 0);
        k_gemm<<<grid, 256, SMEM_BYTES>>>(
            a1h[l], a1l[l], p_w1h + w1off, p_w1l + w1off, K1, K1 / 32, /*mode=*/1,
            aptr + (size_t)l * N_PAD * HIDDEN,
            states + (size_t)l * N_NODES * HIDDEN, leak,
            out + (size_t)l * N_NODES * HIDDEN, ohv[l], olv[l]);
    }
}

// round 14
// speedup vs baseline: 1.1073x; 1.1073x over previous
#include <cuda_runtime.h>
#include <cuda_bf16.h>
#include <math.h>
#include <stdint.h>

#define NUM_LAYERS 4
#define N_NODES 50000
#define N_PAD   50048            // 391 * 128
#define N_EDGES 800000
#define IN_FEAT 256
#define HIDDEN  512
#define MTILES  391

// ---------------- CSR scratch ----------------
__device__ int g_deg[N_NODES];
__device__ int g_row_ptr[N_NODES + 1];
__device__ int g_wptr[N_NODES];
__device__ int g_col[N_EDGES];

// ---------------- bf16 split operand buffers ----------------
__device__ __align__(16) __nv_bfloat16 g_xh[(size_t)N_PAD * IN_FEAT];
__device__ __align__(16) __nv_bfloat16 g_xl[(size_t)N_PAD * IN_FEAT];
__device__ __align__(16) __nv_bfloat16 g_agh[(size_t)NUM_LAYERS * N_PAD * HIDDEN];
__device__ __align__(16) __nv_bfloat16 g_agl[(size_t)NUM_LAYERS * N_PAD * HIDDEN];
__device__ __align__(16) __nv_bfloat16 g_o1h[(size_t)N_PAD * HIDDEN];
__device__ __align__(16) __nv_bfloat16 g_o1l[(size_t)N_PAD * HIDDEN];
__device__ __align__(16) __nv_bfloat16 g_o2h[(size_t)N_PAD * HIDDEN];
__device__ __align__(16) __nv_bfloat16 g_o2l[(size_t)N_PAD * HIDDEN];
#define W1_ELEMS (131072 + 3 * 262144)
#define W2_ELEMS (4 * 262144)
__device__ __align__(16) __nv_bfloat16 g_w1h[W1_ELEMS];
__device__ __align__(16) __nv_bfloat16 g_w1l[W1_ELEMS];
__device__ __align__(16) __nv_bfloat16 g_w2h[W2_ELEMS];
__device__ __align__(16) __nv_bfloat16 g_w2l[W2_ELEMS];

// ---------------- helpers ----------------
__device__ __forceinline__ uint32_t smem_u32(const void* p) {
    uint32_t a;
    asm("{ .reg .u64 t; cvta.to.shared.u64 t, %1; cvt.u32.u64 %0, t; }"
        : "=r"(a) : "l"(p));
    return a;
}

__device__ __forceinline__ void cpa16(uint32_t dst, const void* src) {
    asm volatile("cp.async.cg.shared.global [%0], [%1], 16;"
                 :: "r"(dst), "l"(src) : "memory");
}
#define CP_COMMIT() asm volatile("cp.async.commit_group;" ::: "memory")
#define CP_WAIT(n)  asm volatile("cp.async.wait_group %0;" :: "n"(n) : "memory")

#define LDSM4(r0, r1, r2, r3, addr)                                            \
    asm volatile("ldmatrix.sync.aligned.m8n8.x4.shared.b16 {%0,%1,%2,%3}, [%4];" \
                 : "=r"(r0), "=r"(r1), "=r"(r2), "=r"(r3) : "r"(addr))

#define MMA16816(c, a0, a1, a2, a3, b0, b1)                                    \
    asm volatile("mma.sync.aligned.m16n8k16.row.col.f32.bf16.bf16.f32 "        \
                 "{%0,%1,%2,%3},{%4,%5,%6,%7},{%8,%9},{%0,%1,%2,%3};"          \
                 : "+f"((c)[0]), "+f"((c)[1]), "+f"((c)[2]), "+f"((c)[3])      \
                 : "r"(a0), "r"(a1), "r"(a2), "r"(a3), "r"(b0), "r"(b1))

__device__ __forceinline__ void split_bf16(float v, __nv_bfloat16& h, __nv_bfloat16& l) {
    h = __float2bfloat16_rn(v);
    l = __float2bfloat16_rn(v - __bfloat162float(h));
}

// fast tanh: 1 - 2/(e^{2x}+1); abs err ~1e-7
__device__ __forceinline__ float fast_tanh(float x) {
    float t = __expf(2.0f * x);
    return 1.0f - __fdividef(2.0f, t + 1.0f);
}

// ================= CSR build =================
__global__ void k_zero_deg() {
    for (int i = blockIdx.x * blockDim.x + threadIdx.x; i < N_NODES;
         i += gridDim.x * blockDim.x)
        g_deg[i] = 0;
}

__global__ void k_hist(const int* __restrict__ ei) {
    int e = blockIdx.x * blockDim.x + threadIdx.x;
    if (e < N_EDGES) {
        int dst = ei[N_EDGES + e];
        if ((unsigned)dst < (unsigned)N_NODES) atomicAdd(&g_deg[dst], 1);
    }
}

__global__ void k_scan() {
    __shared__ int buf[1024];
    int t = threadIdx.x;
    int carry = 0;
    for (int base = 0; base < N_NODES; base += 1024) {
        int i = base + t;
        int v = (i < N_NODES) ? g_deg[i] : 0;
        buf[t] = v;
        __syncthreads();
#pragma unroll
        for (int off = 1; off < 1024; off <<= 1) {
            int tmp = (t >= off) ? buf[t - off] : 0;
            __syncthreads();
            buf[t] += tmp;
            __syncthreads();
        }
        int incl = buf[t];
        if (i < N_NODES) {
            g_row_ptr[i + 1] = carry + incl;
            g_wptr[i]        = carry + incl - v;
        }
        carry += buf[1023];
        __syncthreads();
    }
    if (t == 0) g_row_ptr[0] = 0;
}

__global__ void k_scatter(const int* __restrict__ ei) {
    int e = blockIdx.x * blockDim.x + threadIdx.x;
    if (e < N_EDGES) {
        int src = ei[e];
        int dst = ei[N_EDGES + e];
        if ((unsigned)dst < (unsigned)N_NODES && (unsigned)src < (unsigned)N_NODES) {
            int pos = atomicAdd(&g_wptr[dst], 1);
            g_col[pos] = src;
        }
    }
}

// ================= conversions =================
__global__ void k_convert_x(const float* __restrict__ x) {
    const int groups = N_PAD * IN_FEAT / 4;
    for (int g = blockIdx.x * blockDim.x + threadIdx.x; g < groups;
         g += gridDim.x * blockDim.x) {
        int e = g * 4;
        int m = e / IN_FEAT;
        float4 v = make_float4(0.f, 0.f, 0.f, 0.f);
        if (m < N_NODES) v = *(const float4*)&x[e];
        __nv_bfloat16 h0, h1, h2, h3, l0, l1, l2, l3;
        split_bf16(v.x, h0, l0); split_bf16(v.y, h1, l1);
        split_bf16(v.z, h2, l2); split_bf16(v.w, h3, l3);
        *(__nv_bfloat162*)&g_xh[e]     = __halves2bfloat162(h0, h1);
        *(__nv_bfloat162*)&g_xh[e + 2] = __halves2bfloat162(h2, h3);
        *(__nv_bfloat162*)&g_xl[e]     = __halves2bfloat162(l0, l1);
        *(__nv_bfloat162*)&g_xl[e + 2] = __halves2bfloat162(l2, l3);
    }
}

__global__ void k_convert_w(const float* __restrict__ Wi0,
                            const float* __restrict__ Wi_rest,
                            const float* __restrict__ Wr) {
    for (int g = blockIdx.x * blockDim.x + threadIdx.x; g < W1_ELEMS / 4;
         g += gridDim.x * blockDim.x) {
        int e = g * 4;
        float4 v = (e < 131072) ? *(const float4*)&Wi0[e]
                                : *(const float4*)&Wi_rest[e - 131072];
        __nv_bfloat16 h0, h1, h2, h3, l0, l1, l2, l3;
        split_bf16(v.x, h0, l0); split_bf16(v.y, h1, l1);
        split_bf16(v.z, h2, l2); split_bf16(v.w, h3, l3);
        *(__nv_bfloat162*)&g_w1h[e]     = __halves2bfloat162(h0, h1);
        *(__nv_bfloat162*)&g_w1h[e + 2] = __halves2bfloat162(h2, h3);
        *(__nv_bfloat162*)&g_w1l[e]     = __halves2bfloat162(l0, l1);
        *(__nv_bfloat162*)&g_w1l[e + 2] = __halves2bfloat162(l2, l3);
    }
    for (int g = blockIdx.x * blockDim.x + threadIdx.x; g < W2_ELEMS / 4;
         g += gridDim.x * blockDim.x) {
        int e = g * 4;
        float4 v = *(const float4*)&Wr[e];
        __nv_bfloat16 h0, h1, h2, h3, l0, l1, l2, l3;
        split_bf16(v.x, h0, l0); split_bf16(v.y, h1, l1);
        split_bf16(v.z, h2, l2); split_bf16(v.w, h3, l3);
        *(__nv_bfloat162*)&g_w2h[e]     = __halves2bfloat162(h0, h1);
        *(__nv_bfloat162*)&g_w2h[e + 2] = __halves2bfloat162(h2, h3);
        *(__nv_bfloat162*)&g_w2l[e]     = __halves2bfloat162(l0, l1);
        *(__nv_bfloat162*)&g_w2l[e + 2] = __halves2bfloat162(l2, l3);
    }
}

// ================= aggregation: 256-thread / 2-node CTAs ====================
// Designed to co-reside with the reg-capped GEMM: __launch_bounds__(256, 8)
// forces <=32 regs/thread, so one CTA = 8192 regs = the per-SM gap left by
// two 110-reg GEMM CTAs. 8 warps double the per-CTA outstanding-load budget
// vs the old 4-warp version (per-warp M_max ~55 was the overlap bottleneck).
__global__ __launch_bounds__(256, 8)
void k_aggr(const float* __restrict__ states_layer,
            __nv_bfloat16* __restrict__ agh,
            __nv_bfloat16* __restrict__ agl)
{
    const int half = threadIdx.x >> 7;           // 0..1
    const int t    = threadIdx.x & 127;          // float4 column
    const int node = blockIdx.x * 2 + half;      // < N_PAD
    const float4* S = (const float4*)states_layer;

    float4 acc = make_float4(0.f, 0.f, 0.f, 0.f);
    if (node < N_NODES) {
        int e   = g_row_ptr[node];
        int end = g_row_ptr[node + 1];
        for (; e + 2 <= end; e += 2) {
            int s0 = g_col[e], s1 = g_col[e + 1];
            float4 v0 = S[(size_t)s0 * (HIDDEN / 4) + t];
            float4 v1 = S[(size_t)s1 * (HIDDEN / 4) + t];
            acc.x += v0.x + v1.x;
            acc.y += v0.y + v1.y;
            acc.z += v0.z + v1.z;
            acc.w += v0.w + v1.w;
        }
        if (e < end) {
            float4 v = S[(size_t)g_col[e] * (HIDDEN / 4) + t];
            acc.x += v.x; acc.y += v.y; acc.z += v.z; acc.w += v.w;
        }
    }
    size_t o = (size_t)node * HIDDEN + t * 4;
    __nv_bfloat16 h0, h1, h2, h3, l0, l1, l2, l3;
    split_bf16(acc.x, h0, l0); split_bf16(acc.y, h1, l1);
    split_bf16(acc.z, h2, l2); split_bf16(acc.w, h3, l3);
    *(__nv_bfloat162*)&agh[o]     = __halves2bfloat162(h0, h1);
    *(__nv_bfloat162*)&agh[o + 2] = __halves2bfloat162(h2, h3);
    *(__nv_bfloat162*)&agl[o]     = __halves2bfloat162(l0, l1);
    *(__nv_bfloat162*)&agl[o + 2] = __halves2bfloat162(l2, l3);
}

// ================= mma.sync dual-GEMM + tanh epilogue =================
// CTA tile 128x128x32; 8 warps 2(M)x4(N); warp tile 64x32.
// 2-stage cp.async double buffer = 81920 B SMEM => 2 CTAs/SM.
// Operand pointers are kernel ARGS (const bank / uniform regs) — frees GPRs
// vs the old in-kernel selector chains, keeping the 110-reg cap spill-free.
#define ROWP 40
#define TE   (128 * ROWP)              // elems per tile = 5120
#define STAGE_E (4 * TE)               // elems per stage = 20480
#define SMEM_BYTES (2 * STAGE_E * 2)   // 81920 B

__device__ __forceinline__ void load_stage(
    uint32_t sbase,
    const __nv_bfloat16* __restrict__ Ah, const __nv_bfloat16* __restrict__ Al,
    const __nv_bfloat16* __restrict__ Bh, const __nv_bfloat16* __restrict__ Bl,
    int bm, int n0, int kof, int K, int tid)
{
#pragma unroll
    for (int j = 0; j < 2; j++) {
        int idx = tid + j * 256;   // 0..511
        int r = idx >> 2;
        int c = idx & 3;
        uint32_t d = sbase + (uint32_t)(r * ROWP + c * 8) * 2;
        size_t ga = (size_t)(bm + r) * K + kof + c * 8;
        size_t gb = (size_t)(n0 + r) * K + kof + c * 8;
        cpa16(d,              Ah + ga);
        cpa16(d + TE * 2,     Al + ga);
        cpa16(d + 2 * TE * 2, Bh + gb);
        cpa16(d + 3 * TE * 2, Bl + gb);
    }
}

__global__ __launch_bounds__(296, 2)
void k_gemm_mma(const __nv_bfloat16* __restrict__ a1h,
                const __nv_bfloat16* __restrict__ a1l,
                const __nv_bfloat16* __restrict__ b1h,
                const __nv_bfloat16* __restrict__ b1l,
                const __nv_bfloat16* __restrict__ a2h,
                const __nv_bfloat16* __restrict__ a2l,
                const __nv_bfloat16* __restrict__ b2h,
                const __nv_bfloat16* __restrict__ b2l,
                int K1, int c1,
                const float* __restrict__ s_old,
                const float* __restrict__ leak,
                float* __restrict__ outp,
                __nv_bfloat16* __restrict__ oh,
                __nv_bfloat16* __restrict__ ol)
{
    extern __shared__ __nv_bfloat16 smem[];
    const uint32_t sm0 = smem_u32(smem);

    const int tid  = threadIdx.x;
    const int wid  = tid >> 5;
    const int lane = tid & 31;
    const int wm   = wid & 1;       // 0..1 (M)
    const int wn   = wid >> 1;      // 0..3 (N)
    const int bm   = blockIdx.y * 128;
    const int n0   = blockIdx.x * 128;

    float acc[4][4][4];
#pragma unroll
    for (int i = 0; i < 4; i++)
#pragma unroll
        for (int j = 0; j < 4; j++)
#pragma unroll
            for (int q = 0; q < 4; q++) acc[i][j][q] = 0.f;

    const int ctot = c1 + 16;

    // prologue: stage 0 = phase-1 chunk 0
    load_stage(sm0, a1h, a1l, b1h, b1l, bm, n0, 0, K1, tid);
    CP_COMMIT();

    // ldmatrix lane-address components
    const int arow = (lane & 7) + ((lane >> 3) & 1) * 8;   // + wm*64 + mi*16
    const int acol = (lane >> 4) * 8;                       // + ks*16
    const int brow = (lane & 7) + (lane >> 4) * 8;          // + wn*32 + ng2*16
    const int bcol = ((lane >> 3) & 1) * 8;                 // + ks*16

    for (int ci = 0; ci < ctot; ci++) {
        if (ci + 1 < ctot) {
            int cj = ci + 1;
            uint32_t sb = sm0 + (uint32_t)((cj & 1) * STAGE_E) * 2;
            if (cj < c1)
                load_stage(sb, a1h, a1l, b1h, b1l, bm, n0, cj * 32, K1, tid);
            else
                load_stage(sb, a2h, a2l, b2h, b2l, bm, n0, (cj - c1) * 32,
                           HIDDEN, tid);
            CP_COMMIT();
            CP_WAIT(1);
        } else {
            CP_WAIT(0);
        }
        __syncthreads();

        const uint32_t sb = sm0 + (uint32_t)((ci & 1) * STAGE_E) * 2;
        const uint32_t aB = sb + (uint32_t)((wm * 64 + arow) * ROWP + acol) * 2;
        const uint32_t bB = sb + (uint32_t)(2 * TE + (wn * 32 + brow) * ROWP + bcol) * 2;

#pragma unroll
        for (int ks = 0; ks < 2; ks++) {
            // staged fragments: af holds A-hi first, then is REUSED for A-lo.
            uint32_t af[4][4], bh[4][2], bl[4][2];
#pragma unroll
            for (int g2 = 0; g2 < 2; g2++) {
                uint32_t bd = bB + (uint32_t)(g2 * 16 * ROWP + ks * 16) * 2;
                uint32_t t0, t1, t2, t3;
                LDSM4(t0, t1, t2, t3, bd);
                bh[2 * g2][0] = t0; bh[2 * g2][1] = t1;
                bh[2 * g2 + 1][0] = t2; bh[2 * g2 + 1][1] = t3;
                LDSM4(t0, t1, t2, t3, bd + TE * 2);
                bl[2 * g2][0] = t0; bl[2 * g2][1] = t1;
                bl[2 * g2 + 1][0] = t2; bl[2 * g2 + 1][1] = t3;
            }
#pragma unroll
            for (int mi = 0; mi < 4; mi++) {
                uint32_t ad = aB + (uint32_t)(mi * 16 * ROWP + ks * 16) * 2;
                LDSM4(af[mi][0], af[mi][1], af[mi][2], af[mi][3], ad);
            }
            // hh: Ah * Bh
#pragma unroll
            for (int mi = 0; mi < 4; mi++)
#pragma unroll
                for (int ni = 0; ni < 4; ni++)
                    MMA16816(acc[mi][ni], af[mi][0], af[mi][1], af[mi][2], af[mi][3],
                             bh[ni][0], bh[ni][1]);
            // hl: Ah * Bl
#pragma unroll
            for (int mi = 0; mi < 4; mi++)
#pragma unroll
                for (int ni = 0; ni < 4; ni++)
                    MMA16816(acc[mi][ni], af[mi][0], af[mi][1], af[mi][2], af[mi][3],
                             bl[ni][0], bl[ni][1]);
            // reload A-lo into af, then lh: Al * Bh
#pragma unroll
            for (int mi = 0; mi < 4; mi++) {
                uint32_t ad = aB + (uint32_t)(mi * 16 * ROWP + ks * 16) * 2 + TE * 2;
                LDSM4(af[mi][0], af[mi][1], af[mi][2], af[mi][3], ad);
            }
#pragma unroll
            for (int mi = 0; mi < 4; mi++)
#pragma unroll
                for (int ni = 0; ni < 4; ni++)
                    MMA16816(acc[mi][ni], af[mi][0], af[mi][1], af[mi][2], af[mi][3],
                             bh[ni][0], bh[ni][1]);
        }
        __syncthreads();
    }

    // ---------------- epilogue ----------------
    const float a   = leak[0];
    const float oma = 1.0f - a;
#pragma unroll
    for (int mi = 0; mi < 4; mi++) {
#pragma unroll
        for (int h = 0; h < 2; h++) {
            int mm = bm + wm * 64 + mi * 16 + (lane >> 2) + h * 8;
            bool valid = (mm < N_NODES);
            size_t rowb = (size_t)mm * HIDDEN + n0 + wn * 32 + (lane & 3) * 2;
#pragma unroll
            for (int ni = 0; ni < 4; ni++) {
                size_t off = rowb + ni * 8;
                if (valid) {
                    float c0 = acc[mi][ni][2 * h];
                    float c1 = acc[mi][ni][2 * h + 1];
                    float2 s = *(const float2*)&s_old[off];
                    float o0 = a * fast_tanh(c0) + oma * s.x;
                    float o1 = a * fast_tanh(c1) + oma * s.y;
                    *(float2*)&outp[off] = make_float2(o0, o1);
                    if (oh) {
                        __nv_bfloat16 h0, h1, l0, l1;
                        split_bf16(o0, h0, l0);
                        split_bf16(o1, h1, l1);
                        *(__nv_bfloat162*)&oh[off] = __halves2bfloat162(h0, h1);
                        *(__nv_bfloat162*)&ol[off] = __halves2bfloat162(l0, l1);
                    }
                } else if (oh) {
                    __nv_bfloat162 z =
                        __halves2bfloat162(__float2bfloat16_rn(0.f),
                                           __float2bfloat16_rn(0.f));
                    *(__nv_bfloat162*)&oh[off] = z;
                    *(__nv_bfloat162*)&ol[off] = z;
                }
            }
        }
    }
}

// ================= launch =================
extern "C" void kernel_launch(void* const* d_in, const int* in_sizes, int n_in,
                              void* d_out, int out_size)
{
    const int*   ei      = (const int*)d_in[0];       // [2, E] int32
    const float* x       = (const float*)d_in[1];     // [N, 256]
    const float* states  = (const float*)d_in[2];     // [4, N, 512]
    const float* Wi0     = (const float*)d_in[3];     // [512, 256]
    const float* Wi_rest = (const float*)d_in[4];     // [3, 512, 512]
    const float* Wr      = (const float*)d_in[5];     // [4, 512, 512]
    const float* leak    = (const float*)d_in[6];     // [1]
    float*       out     = (float*)d_out;             // [4, N, 512]

    (void)in_sizes; (void)n_in; (void)out_size;

    // one-time setup; ALL __device__ symbol addresses via cudaGetSymbolAddress
    // (round-12 lesson: bare symbols in host code are host shadows; GB300 ATS
    // silently dereferences them)
    static cudaStream_t sAg = nullptr;
    static cudaEvent_t evFork = nullptr;
    static cudaEvent_t evA[NUM_LAYERS];
    static __nv_bfloat16 *p_xh, *p_xl, *p_agh, *p_agl;
    static __nv_bfloat16 *p_o1h, *p_o1l, *p_o2h, *p_o2l;
    static __nv_bfloat16 *p_w1h, *p_w1l, *p_w2h, *p_w2l;
    if (sAg == nullptr) {
        cudaFuncSetAttribute(k_gemm_mma,
                             cudaFuncAttributeMaxDynamicSharedMemorySize,
                             SMEM_BYTES);
        cudaStreamCreateWithFlags(&sAg, cudaStreamNonBlocking);
        cudaEventCreateWithFlags(&evFork, cudaEventDisableTiming);
        for (int l = 0; l < NUM_LAYERS; l++)
            cudaEventCreateWithFlags(&evA[l], cudaEventDisableTiming);
        cudaGetSymbolAddress((void**)&p_xh,  g_xh);
        cudaGetSymbolAddress((void**)&p_xl,  g_xl);
        cudaGetSymbolAddress((void**)&p_agh, g_agh);
        cudaGetSymbolAddress((void**)&p_agl, g_agl);
        cudaGetSymbolAddress((void**)&p_o1h, g_o1h);
        cudaGetSymbolAddress((void**)&p_o1l, g_o1l);
        cudaGetSymbolAddress((void**)&p_o2h, g_o2h);
        cudaGetSymbolAddress((void**)&p_o2l, g_o2l);
        cudaGetSymbolAddress((void**)&p_w1h, g_w1h);
        cudaGetSymbolAddress((void**)&p_w1l, g_w1l);
        cudaGetSymbolAddress((void**)&p_w2h, g_w2h);
        cudaGetSymbolAddress((void**)&p_w2l, g_w2l);
    }

    // ---- main stream: CSR build ----
    k_zero_deg<<<128, 256>>>();
    k_hist<<<(N_EDGES + 255) / 256, 256>>>(ei);
    k_scan<<<1, 1024>>>();
    k_scatter<<<(N_EDGES + 255) / 256, 256>>>(ei);

    // ---- legal capture fork (event recorded on origin stream) ----
    cudaEventRecord(evFork, 0);
    cudaStreamWaitEvent(sAg, evFork, 0);

    // ---- side stream: 4 layer aggregations (8-warp, 32-reg CTAs) ----
    for (int l = 0; l < NUM_LAYERS; l++) {
        size_t off = (size_t)l * N_PAD * HIDDEN;
        k_aggr<<<N_PAD / 2, 256, 0, sAg>>>(states + (size_t)l * N_NODES * HIDDEN,
                                           p_agh + off, p_agl + off);
        cudaEventRecord(evA[l], sAg);
    }

    // ---- main stream: conversions (overlap with aggr0) ----
    k_convert_x<<<4096, 256>>>(x);
    k_convert_w<<<1024, 256>>>(Wi0, Wi_rest, Wr);

    // ---- main stream: sequential GEMM chain; GEMM l waits on aggr l ----
    const __nv_bfloat16* a1h[4] = {p_xh, p_o1h, p_o2h, p_o1h};
    const __nv_bfloat16* a1l[4] = {p_xl, p_o1l, p_o2l, p_o1l};
    __nv_bfloat16* ohv[4] = {p_o1h, p_o2h, p_o1h, nullptr};
    __nv_bfloat16* olv[4] = {p_o1l, p_o2l, p_o1l, nullptr};
    dim3 grid(HIDDEN / 128, MTILES);
    for (int l = 0; l < NUM_LAYERS; l++) {
        int K1 = (l == 0) ? IN_FEAT : HIDDEN;
        int c1 = K1 / 32;
        const size_t w1off = (l == 0) ? 0 : (size_t)131072 + (size_t)(l - 1) * 262144;
        const size_t aoff  = (size_t)l * N_PAD * HIDDEN;
        cudaStreamWaitEvent(0, evA[l], 0);
        k_gemm_mma<<<grid, 256, SMEM_BYTES>>>(
            a1h[l], a1l[l], p_w1h + w1off, p_w1l + w1off,
            p_agh + aoff, p_agl + aoff,
            p_w2h + (size_t)l * 262144, p_w2l + (size_t)l * 262144,
            K1, c1,
            states + (size_t)l * N_NODES * HIDDEN, leak,
            out + (size_t)l * N_NODES * HIDDEN, ohv[l], olv[l]);
    }
}